// round 10
// baseline (speedup 1.0000x reference)
#include <cuda_runtime.h>
#include <cuda_fp16.h>

// ---------------------------------------------------------------------------
// ExpanderSimpleGraphSageLayer — CSR gather, fp16 staging
// R10: pair-gather LDG.128 (2 rows/load, 16-row batches), vectorized CSR build
//
// Inputs (metadata order):
//   d_in[0] h        float32 [N, D]        N=100000, D=128
//   d_in[1] b        float32 [N, D]
//   d_in[2] norm     float32 [N, 1]
//   d_in[3] edge_src int32   [E]           E=1600000
//   d_in[4] edge_dst int32   [E]
// Output: h_out [N,D] followed by b_out [N,2D]  (float32, N*3D elements)
// ---------------------------------------------------------------------------

#define NN 100000
#define DD 128
#define EE 1600000

#define SCAN_TPB 256
#define SCAN_IPT 4
#define SCAN_PER_BLK (SCAN_TPB * SCAN_IPT)                 // 1024
#define SCAN_NB ((NN + SCAN_PER_BLK - 1) / SCAN_PER_BLK)   // 98  (< 148 SMs)

static __device__ __align__(16) __half g_hn16[NN * DD];  // fp16(h*norm), 25.6MB
static __device__ int    g_cursor[NN];       // atomic fill cursor
static __device__ int    g_rowstart[NN + 1]; // CSR row offsets
static __device__ int    g_csr[EE];          // src ids grouped by dst

// zero-region: [count (NN int)] [scan state (SCAN_NB u64)] — one memset
static __device__ __align__(16) unsigned char g_zero[NN * 4 + SCAN_NB * 8];
#define G_COUNT ((int*)g_zero)
#define G_STATE ((unsigned long long*)(g_zero + NN * 4))
// state word: (status << 32) | value.  status: 0=empty, 1=aggregate, 2=inclusive

// ---- streaming load/store helpers -----------------------------------------
__device__ __forceinline__ float4 ldcs4(const float4* p) {
    float4 v;
    asm volatile("ld.global.cs.v4.f32 {%0,%1,%2,%3}, [%4];"
                 : "=f"(v.x), "=f"(v.y), "=f"(v.z), "=f"(v.w) : "l"(p));
    return v;
}
__device__ __forceinline__ void stcs4(float4* p, float4 v) {
    asm volatile("st.global.cs.v4.f32 [%0], {%1,%2,%3,%4};"
                 :: "l"(p), "f"(v.x), "f"(v.y), "f"(v.z), "f"(v.w) : "memory");
}

// accumulate 8 halves (one uint4) into 8 fp32
__device__ __forceinline__ void acc8(float* a, uint4 v) {
    float2 f0 = __half22float2(*reinterpret_cast<__half2*>(&v.x));
    float2 f1 = __half22float2(*reinterpret_cast<__half2*>(&v.y));
    float2 f2 = __half22float2(*reinterpret_cast<__half2*>(&v.z));
    float2 f3 = __half22float2(*reinterpret_cast<__half2*>(&v.w));
    a[0] += f0.x; a[1] += f0.y; a[2] += f1.x; a[3] += f1.y;
    a[4] += f2.x; a[5] += f2.y; a[6] += f3.x; a[7] += f3.y;
}

// ---- phase 1: fused  prescale (blocks [0,preB))  ∥  hist (rest) -----------
__global__ void __launch_bounds__(256)
fused_pre_hist_kernel(const float* __restrict__ h, const float* __restrict__ norm,
                      const int* __restrict__ dst, int E, int preB)
{
    if ((int)blockIdx.x < preB) {
        int idx = blockIdx.x * 256 + threadIdx.x;          // one float4
        if (idx >= NN * (DD / 4)) return;
        int row = idx >> 5;                                // 32 float4 per row
        float4 v = ldcs4(reinterpret_cast<const float4*>(h) + idx);
        float  s = __ldg(norm + row);
        __half2 lo = __floats2half2_rn(v.x * s, v.y * s);
        __half2 hi = __floats2half2_rn(v.z * s, v.w * s);
        uint2 u;
        u.x = *reinterpret_cast<unsigned*>(&lo);
        u.y = *reinterpret_cast<unsigned*>(&hi);
        reinterpret_cast<uint2*>(g_hn16)[idx] = u;
    } else {
        int base = ((blockIdx.x - preB) * 256 + threadIdx.x) * 8;
        if (base + 8 <= E) {
            const int4* d4 = reinterpret_cast<const int4*>(dst + base);
            int4 da = __ldg(d4), db = __ldg(d4 + 1);
            atomicAdd(&G_COUNT[da.x], 1); atomicAdd(&G_COUNT[da.y], 1);
            atomicAdd(&G_COUNT[da.z], 1); atomicAdd(&G_COUNT[da.w], 1);
            atomicAdd(&G_COUNT[db.x], 1); atomicAdd(&G_COUNT[db.y], 1);
            atomicAdd(&G_COUNT[db.z], 1); atomicAdd(&G_COUNT[db.w], 1);
        } else {
            for (int e = base; e < E; ++e)
                atomicAdd(&G_COUNT[__ldg(dst + e)], 1);
        }
    }
}

// ---- phase 2: single-pass exclusive scan (decoupled lookback) --------------
__global__ void __launch_bounds__(SCAN_TPB)
scan_onepass_kernel(int E)
{
    int blk  = blockIdx.x;
    int lane = threadIdx.x & 31, wid = threadIdx.x >> 5;
    int base = blk * SCAN_PER_BLK + threadIdx.x * SCAN_IPT;

    int c[SCAN_IPT];
    if (base + SCAN_IPT <= NN) {
        int4 cv = *reinterpret_cast<const int4*>(G_COUNT + base);
        c[0] = cv.x; c[1] = cv.y; c[2] = cv.z; c[3] = cv.w;
    } else {
        #pragma unroll
        for (int i = 0; i < SCAN_IPT; ++i) {
            int idx = base + i;
            c[i] = (idx < NN) ? G_COUNT[idx] : 0;
        }
    }
    int t0 = c[0];
    int t1 = t0 + c[1];
    int t2 = t1 + c[2];
    int t3 = t2 + c[3];
    int tot = t3;

    // warp inclusive scan of per-thread totals
    int x = tot;
    #pragma unroll
    for (int d = 1; d < 32; d <<= 1) {
        int y = __shfl_up_sync(0xffffffffu, x, d);
        if (lane >= d) x += y;
    }
    int warp_excl = x - tot;

    __shared__ int wsum[SCAN_TPB / 32];
    __shared__ int woff[SCAN_TPB / 32];
    __shared__ int sh_btotal;
    __shared__ unsigned sh_excl;
    if (lane == 31) wsum[wid] = x;
    __syncthreads();
    if (threadIdx.x == 0) {
        int r = 0;
        #pragma unroll
        for (int j = 0; j < SCAN_TPB / 32; ++j) { woff[j] = r; r += wsum[j]; }
        sh_btotal = r;
        sh_excl = 0;
    }
    __syncthreads();
    int btotal = sh_btotal;

    if (blk == 0) {
        if (threadIdx.x == 0) {
            __threadfence();
            *(volatile unsigned long long*)&G_STATE[0] =
                (2ull << 32) | (unsigned)btotal;
        }
    } else if (wid == 0) {
        if (lane == 0) {
            __threadfence();
            *(volatile unsigned long long*)&G_STATE[blk] =
                (1ull << 32) | (unsigned)btotal;
        }
        unsigned running = 0;
        int idx = blk - 1;
        for (;;) {
            int j = idx - lane;
            bool valid = j >= 0;
            unsigned long long st;
            for (;;) {
                st = valid ? *(volatile const unsigned long long*)&G_STATE[j]
                           : (2ull << 32);
                if (!__any_sync(0xffffffffu, (unsigned)(st >> 32) == 0u)) break;
            }
            unsigned stat = (unsigned)(st >> 32);
            unsigned val  = (unsigned)st;
            unsigned mask2 = __ballot_sync(0xffffffffu, stat == 2u);
            if (mask2) {
                int firstIncl = __ffs(mask2) - 1;   // closest inclusive
                unsigned contrib = (lane <= firstIncl) ? val : 0u;
                #pragma unroll
                for (int m = 16; m; m >>= 1)
                    contrib += __shfl_xor_sync(0xffffffffu, contrib, m);
                running += contrib;
                break;
            } else {
                unsigned contrib = val;
                #pragma unroll
                for (int m = 16; m; m >>= 1)
                    contrib += __shfl_xor_sync(0xffffffffu, contrib, m);
                running += contrib;
                idx -= 32;
            }
        }
        if (lane == 0) {
            sh_excl = running;
            __threadfence();
            *(volatile unsigned long long*)&G_STATE[blk] =
                (2ull << 32) | (unsigned)(running + btotal);
        }
    }
    __syncthreads();
    unsigned excl = sh_excl;

    int off = (int)excl + woff[wid] + warp_excl;
    int ex[SCAN_IPT] = { off, off + t0, off + t1, off + t2 };
    #pragma unroll
    for (int i = 0; i < SCAN_IPT; ++i) {
        int idx = base + i;
        if (idx < NN) {
            g_rowstart[idx] = ex[i];
            g_cursor[idx]   = ex[i];
        }
    }
    if (blk == 0 && threadIdx.x == 0) g_rowstart[NN] = E;
}

// ---- phase 3: fill CSR (8 independent atomic chains, int4 edge loads) ------
__global__ void __launch_bounds__(256)
fill_kernel(const int* __restrict__ src, const int* __restrict__ dst, int E)
{
    int base = (blockIdx.x * blockDim.x + threadIdx.x) * 8;
    if (base + 8 <= E) {
        const int4* s4 = reinterpret_cast<const int4*>(src + base);
        const int4* d4 = reinterpret_cast<const int4*>(dst + base);
        int4 sa = __ldg(s4), sb = __ldg(s4 + 1);
        int4 da = __ldg(d4), db = __ldg(d4 + 1);
        int s[8] = { sa.x, sa.y, sa.z, sa.w, sb.x, sb.y, sb.z, sb.w };
        int d[8] = { da.x, da.y, da.z, da.w, db.x, db.y, db.z, db.w };
        int p[8];
        #pragma unroll
        for (int i = 0; i < 8; ++i) p[i] = atomicAdd(&g_cursor[d[i]], 1);
        #pragma unroll
        for (int i = 0; i < 8; ++i) g_csr[p[i]] = s[i];
    } else {
        for (int e = base; e < E; ++e) {
            int d = __ldg(dst + e);
            int p = atomicAdd(&g_cursor[d], 1);
            g_csr[p] = __ldg(src + e);
        }
    }
}

// ---- phase 4: fused gather-mean + finalize (one warp per node) -------------
// Pair-gather: half-warp (16 lanes x 16B) covers one 256B row, so each
// LDG.128 fetches TWO rows. Lane holds 8 fp32 accs for cols [8m, 8m+8),
// m = lane&15; fold across halves with shfl_xor(16) at the end.
__global__ void __launch_bounds__(256)
gather_finalize_kernel(const float* __restrict__ h, const float* __restrict__ b,
                       const float* __restrict__ norm, float* __restrict__ out)
{
    int node = (blockIdx.x * blockDim.x + threadIdx.x) >> 5;
    int lane = threadIdx.x & 31;
    if (node >= NN) return;

    int m  = lane & 15;
    int hf = lane >> 4;                    // 0: even rows, 1: odd rows

    int start = __ldg(g_rowstart + node);
    int end   = __ldg(g_rowstart + node + 1);

    const uint4* hn4 = reinterpret_cast<const uint4*>(g_hn16);  // 16 uint4/row
    float a[8] = {0.f, 0.f, 0.f, 0.f, 0.f, 0.f, 0.f, 0.f};

    int e = start;
    for (; e + 15 < end; e += 16) {                 // 16 rows, 8 loads in flight
        int s[16];
        #pragma unroll
        for (int i = 0; i < 16; ++i) s[i] = __ldg(g_csr + e + i);
        uint4 v[8];
        #pragma unroll
        for (int j = 0; j < 8; ++j) {
            int row = hf ? s[2 * j + 1] : s[2 * j];
            v[j] = hn4[row * 16 + m];
        }
        #pragma unroll
        for (int j = 0; j < 8; ++j) acc8(a, v[j]);
    }
    if (e + 7 < end) {                              // 8 rows, 4 loads
        int s[8];
        #pragma unroll
        for (int i = 0; i < 8; ++i) s[i] = __ldg(g_csr + e + i);
        uint4 v[4];
        #pragma unroll
        for (int j = 0; j < 4; ++j) {
            int row = hf ? s[2 * j + 1] : s[2 * j];
            v[j] = hn4[row * 16 + m];
        }
        #pragma unroll
        for (int j = 0; j < 4; ++j) acc8(a, v[j]);
        e += 8;
    }
    if (e + 3 < end) {                              // 4 rows, 2 loads
        int s[4];
        #pragma unroll
        for (int i = 0; i < 4; ++i) s[i] = __ldg(g_csr + e + i);
        uint4 v[2];
        #pragma unroll
        for (int j = 0; j < 2; ++j) {
            int row = hf ? s[2 * j + 1] : s[2 * j];
            v[j] = hn4[row * 16 + m];
        }
        acc8(a, v[0]); acc8(a, v[1]);
        e += 4;
    }
    if (e + 1 < end) {                              // 2 rows, 1 load
        int s0 = __ldg(g_csr + e);
        int s1 = __ldg(g_csr + e + 1);
        int row = hf ? s1 : s0;
        acc8(a, hn4[row * 16 + m]);
        e += 2;
    }
    if (e < end) {                                  // last odd row
        int s0 = __ldg(g_csr + e);
        uint4 v = hn4[s0 * 16 + m];
        if (!hf) acc8(a, v);                        // only one half contributes
    }

    // fold halves: every lane ends with full sums for cols [8m, 8m+8)
    #pragma unroll
    for (int i = 0; i < 8; ++i)
        a[i] += __shfl_xor_sync(0xffffffffu, a[i], 16);

    float inv_deg = 1.0f / fmaxf((float)(end - start), 1.0f);
    // this lane's 4 output cols: slot = 2m + hf  (float4 granularity)
    int baseq = hf * 4;
    float4 c;
    c.x = a[baseq + 0] * inv_deg; c.y = a[baseq + 1] * inv_deg;
    c.z = a[baseq + 2] * inv_deg; c.w = a[baseq + 3] * inv_deg;
    int slot = m * 2 + hf;

    float4 bv = ldcs4(reinterpret_cast<const float4*>(b) + node * 32 + slot);

    // sum of squares over concat(b, c): each col counted exactly once
    float ss = bv.x * bv.x + bv.y * bv.y + bv.z * bv.z + bv.w * bv.w
             +  c.x *  c.x +  c.y *  c.y +  c.z *  c.z +  c.w *  c.w;
    #pragma unroll
    for (int mm = 16; mm; mm >>= 1)
        ss += __shfl_xor_sync(0xffffffffu, ss, mm);

    float inv_l2 = 1.0f / fmaxf(sqrtf(ss), 1e-12f);
    float nrm    = __ldg(norm + node);

    // h_out = h + c * norm
    float4 hv = ldcs4(reinterpret_cast<const float4*>(h) + node * 32 + slot);
    float4 ho;
    ho.x = hv.x + c.x * nrm;
    ho.y = hv.y + c.y * nrm;
    ho.z = hv.z + c.z * nrm;
    ho.w = hv.w + c.w * nrm;
    stcs4(reinterpret_cast<float4*>(out) + node * 32 + slot, ho);

    // b_out = concat(b, c) / l2
    float* bout = out + (size_t)NN * DD;
    float4 b1; b1.x = bv.x * inv_l2; b1.y = bv.y * inv_l2;
               b1.z = bv.z * inv_l2; b1.w = bv.w * inv_l2;
    float4 b2; b2.x =  c.x * inv_l2; b2.y =  c.y * inv_l2;
               b2.z =  c.z * inv_l2; b2.w =  c.w * inv_l2;
    stcs4(reinterpret_cast<float4*>(bout) + node * 64 + slot,      b1);
    stcs4(reinterpret_cast<float4*>(bout) + node * 64 + 32 + slot, b2);
}

// ---------------------------------------------------------------------------
extern "C" void kernel_launch(void* const* d_in, const int* in_sizes, int n_in,
                              void* d_out, int out_size)
{
    const float* h    = (const float*)d_in[0];
    const float* b    = (const float*)d_in[1];
    const float* norm = (const float*)d_in[2];
    const int*   esrc = (const int*)  d_in[3];
    const int*   edst = (const int*)  d_in[4];
    float*       out  = (float*)d_out;
    int E = in_sizes[3];
    if (E > EE) E = EE;

    void* zero_ptr = nullptr;
    cudaGetSymbolAddress(&zero_ptr, g_zero);
    cudaMemsetAsync(zero_ptr, 0, (size_t)NN * 4 + SCAN_NB * 8);

    // fused prescale ∥ hist (8 edges/thread in hist)
    int preB  = (NN * (DD / 4) + 255) / 256;            // 12500
    int histB = (E + 2047) / 2048;
    fused_pre_hist_kernel<<<preB + histB, 256>>>(h, norm, edst, E, preB);

    // single-pass scan -> rowstart + cursor
    scan_onepass_kernel<<<SCAN_NB, SCAN_TPB>>>(E);

    // CSR fill (8 edges per thread, vectorized)
    int eb8 = (E / 8 + 255) / 256 + 1;
    fill_kernel<<<eb8, 256>>>(esrc, edst, E);

    // fused gather-mean + finalize: one warp per node
    long long threads = (long long)NN * 32;
    int blocks = (int)((threads + 255) / 256);
    gather_finalize_kernel<<<blocks, 256>>>(h, b, norm, out);
}

// round 12
// speedup vs baseline: 1.0128x; 1.0128x over previous
#include <cuda_runtime.h>
#include <cuda_fp16.h>

// ---------------------------------------------------------------------------
// ExpanderSimpleGraphSageLayer — CSR gather, fp16 staging
// R11: revert gather to uint2 row-loads (R9), split each node across 2 warps
//      (stride-2 edge halves, smem combine) to halve the serial batch chain.
//
// Inputs (metadata order):
//   d_in[0] h        float32 [N, D]        N=100000, D=128
//   d_in[1] b        float32 [N, D]
//   d_in[2] norm     float32 [N, 1]
//   d_in[3] edge_src int32   [E]           E=1600000
//   d_in[4] edge_dst int32   [E]
// Output: h_out [N,D] followed by b_out [N,2D]  (float32, N*3D elements)
// ---------------------------------------------------------------------------

#define NN 100000
#define DD 128
#define EE 1600000

#define SCAN_TPB 256
#define SCAN_IPT 4
#define SCAN_PER_BLK (SCAN_TPB * SCAN_IPT)                 // 1024
#define SCAN_NB ((NN + SCAN_PER_BLK - 1) / SCAN_PER_BLK)   // 98  (< 148 SMs)

static __device__ __align__(16) __half g_hn16[NN * DD];  // fp16(h*norm), 25.6MB
static __device__ int    g_cursor[NN];       // atomic fill cursor
static __device__ int    g_rowstart[NN + 1]; // CSR row offsets
static __device__ int    g_csr[EE];          // src ids grouped by dst

// zero-region: [count (NN int)] [scan state (SCAN_NB u64)] — one memset
static __device__ __align__(16) unsigned char g_zero[NN * 4 + SCAN_NB * 8];
#define G_COUNT ((int*)g_zero)
#define G_STATE ((unsigned long long*)(g_zero + NN * 4))
// state word: (status << 32) | value.  status: 0=empty, 1=aggregate, 2=inclusive

// ---- streaming load/store helpers -----------------------------------------
__device__ __forceinline__ float4 ldcs4(const float4* p) {
    float4 v;
    asm volatile("ld.global.cs.v4.f32 {%0,%1,%2,%3}, [%4];"
                 : "=f"(v.x), "=f"(v.y), "=f"(v.z), "=f"(v.w) : "l"(p));
    return v;
}
__device__ __forceinline__ void stcs4(float4* p, float4 v) {
    asm volatile("st.global.cs.v4.f32 [%0], {%1,%2,%3,%4};"
                 :: "l"(p), "f"(v.x), "f"(v.y), "f"(v.z), "f"(v.w) : "memory");
}

// accumulate 4 halves (one uint2) into float4
__device__ __forceinline__ void accum4(float4& a, uint2 r) {
    float2 f0 = __half22float2(*reinterpret_cast<__half2*>(&r.x));
    float2 f1 = __half22float2(*reinterpret_cast<__half2*>(&r.y));
    a.x += f0.x; a.y += f0.y; a.z += f1.x; a.w += f1.y;
}

// ---- phase 1: fused  prescale (blocks [0,preB))  ∥  hist (rest) -----------
__global__ void __launch_bounds__(256)
fused_pre_hist_kernel(const float* __restrict__ h, const float* __restrict__ norm,
                      const int* __restrict__ dst, int E, int preB)
{
    if ((int)blockIdx.x < preB) {
        int idx = blockIdx.x * 256 + threadIdx.x;          // one float4
        if (idx >= NN * (DD / 4)) return;
        int row = idx >> 5;                                // 32 float4 per row
        float4 v = ldcs4(reinterpret_cast<const float4*>(h) + idx);
        float  s = __ldg(norm + row);
        __half2 lo = __floats2half2_rn(v.x * s, v.y * s);
        __half2 hi = __floats2half2_rn(v.z * s, v.w * s);
        uint2 u;
        u.x = *reinterpret_cast<unsigned*>(&lo);
        u.y = *reinterpret_cast<unsigned*>(&hi);
        reinterpret_cast<uint2*>(g_hn16)[idx] = u;
    } else {
        int base = ((blockIdx.x - preB) * 256 + threadIdx.x) * 8;
        if (base + 8 <= E) {
            const int4* d4 = reinterpret_cast<const int4*>(dst + base);
            int4 da = __ldg(d4), db = __ldg(d4 + 1);
            atomicAdd(&G_COUNT[da.x], 1); atomicAdd(&G_COUNT[da.y], 1);
            atomicAdd(&G_COUNT[da.z], 1); atomicAdd(&G_COUNT[da.w], 1);
            atomicAdd(&G_COUNT[db.x], 1); atomicAdd(&G_COUNT[db.y], 1);
            atomicAdd(&G_COUNT[db.z], 1); atomicAdd(&G_COUNT[db.w], 1);
        } else {
            for (int e = base; e < E; ++e)
                atomicAdd(&G_COUNT[__ldg(dst + e)], 1);
        }
    }
}

// ---- phase 2: single-pass exclusive scan (decoupled lookback) --------------
__global__ void __launch_bounds__(SCAN_TPB)
scan_onepass_kernel(int E)
{
    int blk  = blockIdx.x;
    int lane = threadIdx.x & 31, wid = threadIdx.x >> 5;
    int base = blk * SCAN_PER_BLK + threadIdx.x * SCAN_IPT;

    int c[SCAN_IPT];
    if (base + SCAN_IPT <= NN) {
        int4 cv = *reinterpret_cast<const int4*>(G_COUNT + base);
        c[0] = cv.x; c[1] = cv.y; c[2] = cv.z; c[3] = cv.w;
    } else {
        #pragma unroll
        for (int i = 0; i < SCAN_IPT; ++i) {
            int idx = base + i;
            c[i] = (idx < NN) ? G_COUNT[idx] : 0;
        }
    }
    int t0 = c[0];
    int t1 = t0 + c[1];
    int t2 = t1 + c[2];
    int t3 = t2 + c[3];
    int tot = t3;

    // warp inclusive scan of per-thread totals
    int x = tot;
    #pragma unroll
    for (int d = 1; d < 32; d <<= 1) {
        int y = __shfl_up_sync(0xffffffffu, x, d);
        if (lane >= d) x += y;
    }
    int warp_excl = x - tot;

    __shared__ int wsum[SCAN_TPB / 32];
    __shared__ int woff[SCAN_TPB / 32];
    __shared__ int sh_btotal;
    __shared__ unsigned sh_excl;
    if (lane == 31) wsum[wid] = x;
    __syncthreads();
    if (threadIdx.x == 0) {
        int r = 0;
        #pragma unroll
        for (int j = 0; j < SCAN_TPB / 32; ++j) { woff[j] = r; r += wsum[j]; }
        sh_btotal = r;
        sh_excl = 0;
    }
    __syncthreads();
    int btotal = sh_btotal;

    if (blk == 0) {
        if (threadIdx.x == 0) {
            __threadfence();
            *(volatile unsigned long long*)&G_STATE[0] =
                (2ull << 32) | (unsigned)btotal;
        }
    } else if (wid == 0) {
        if (lane == 0) {
            __threadfence();
            *(volatile unsigned long long*)&G_STATE[blk] =
                (1ull << 32) | (unsigned)btotal;
        }
        unsigned running = 0;
        int idx = blk - 1;
        for (;;) {
            int j = idx - lane;
            bool valid = j >= 0;
            unsigned long long st;
            for (;;) {
                st = valid ? *(volatile const unsigned long long*)&G_STATE[j]
                           : (2ull << 32);
                if (!__any_sync(0xffffffffu, (unsigned)(st >> 32) == 0u)) break;
            }
            unsigned stat = (unsigned)(st >> 32);
            unsigned val  = (unsigned)st;
            unsigned mask2 = __ballot_sync(0xffffffffu, stat == 2u);
            if (mask2) {
                int firstIncl = __ffs(mask2) - 1;   // closest inclusive
                unsigned contrib = (lane <= firstIncl) ? val : 0u;
                #pragma unroll
                for (int m = 16; m; m >>= 1)
                    contrib += __shfl_xor_sync(0xffffffffu, contrib, m);
                running += contrib;
                break;
            } else {
                unsigned contrib = val;
                #pragma unroll
                for (int m = 16; m; m >>= 1)
                    contrib += __shfl_xor_sync(0xffffffffu, contrib, m);
                running += contrib;
                idx -= 32;
            }
        }
        if (lane == 0) {
            sh_excl = running;
            __threadfence();
            *(volatile unsigned long long*)&G_STATE[blk] =
                (2ull << 32) | (unsigned)(running + btotal);
        }
    }
    __syncthreads();
    unsigned excl = sh_excl;

    int off = (int)excl + woff[wid] + warp_excl;
    int ex[SCAN_IPT] = { off, off + t0, off + t1, off + t2 };
    #pragma unroll
    for (int i = 0; i < SCAN_IPT; ++i) {
        int idx = base + i;
        if (idx < NN) {
            g_rowstart[idx] = ex[i];
            g_cursor[idx]   = ex[i];
        }
    }
    if (blk == 0 && threadIdx.x == 0) g_rowstart[NN] = E;
}

// ---- phase 3: fill CSR (8 independent atomic chains, int4 edge loads) ------
__global__ void __launch_bounds__(256)
fill_kernel(const int* __restrict__ src, const int* __restrict__ dst, int E)
{
    int base = (blockIdx.x * blockDim.x + threadIdx.x) * 8;
    if (base + 8 <= E) {
        const int4* s4 = reinterpret_cast<const int4*>(src + base);
        const int4* d4 = reinterpret_cast<const int4*>(dst + base);
        int4 sa = __ldg(s4), sb = __ldg(s4 + 1);
        int4 da = __ldg(d4), db = __ldg(d4 + 1);
        int s[8] = { sa.x, sa.y, sa.z, sa.w, sb.x, sb.y, sb.z, sb.w };
        int d[8] = { da.x, da.y, da.z, da.w, db.x, db.y, db.z, db.w };
        int p[8];
        #pragma unroll
        for (int i = 0; i < 8; ++i) p[i] = atomicAdd(&g_cursor[d[i]], 1);
        #pragma unroll
        for (int i = 0; i < 8; ++i) g_csr[p[i]] = s[i];
    } else {
        for (int e = base; e < E; ++e) {
            int d = __ldg(dst + e);
            int p = atomicAdd(&g_cursor[d], 1);
            g_csr[p] = __ldg(src + e);
        }
    }
}

// ---- phase 4: gather-mean + finalize, TWO warps per node -------------------
// Warp pair (2n, 2n+1): warp `half` processes edges start+2k+half (stride 2).
// Per-lane acc is float4 over this lane's 4 columns (uint2 of halves).
// Odd warp stores partial to smem; even warp combines and finalizes (as R9).
__global__ void __launch_bounds__(256)
gather_finalize_kernel(const float* __restrict__ h, const float* __restrict__ b,
                       const float* __restrict__ norm, float* __restrict__ out)
{
    __shared__ float4 sh_acc[4][32];                 // one slot per warp pair

    int gw   = (blockIdx.x * blockDim.x + threadIdx.x) >> 5;
    int node = gw >> 1;
    int half = gw & 1;
    int lane = threadIdx.x & 31;
    int wid  = threadIdx.x >> 5;                     // 0..7
    int pair = wid >> 1;                             // 0..3
    bool valid = node < NN;

    const uint2* hn = reinterpret_cast<const uint2*>(g_hn16);   // 32 uint2/row
    float4 acc = make_float4(0.f, 0.f, 0.f, 0.f);
    int start = 0, end = 0;

    if (valid) {
        start = __ldg(g_rowstart + node);
        end   = __ldg(g_rowstart + node + 1);
        int len = end - start;
        int cnt = (len + 1 - half) >> 1;             // half0 ceil, half1 floor
        const int* my = g_csr + start + half;        // stride-2 list

        int k = 0;
        for (; k + 7 < cnt; k += 8) {                // 8 rows in flight
            int s[8];
            #pragma unroll
            for (int i = 0; i < 8; ++i) s[i] = __ldg(my + 2 * (k + i));
            uint2 r[8];
            #pragma unroll
            for (int i = 0; i < 8; ++i) r[i] = hn[s[i] * 32 + lane];
            #pragma unroll
            for (int i = 0; i < 8; ++i) accum4(acc, r[i]);
        }
        if (k + 3 < cnt) {                           // 4-wide tail
            int s[4];
            #pragma unroll
            for (int i = 0; i < 4; ++i) s[i] = __ldg(my + 2 * (k + i));
            uint2 r[4];
            #pragma unroll
            for (int i = 0; i < 4; ++i) r[i] = hn[s[i] * 32 + lane];
            #pragma unroll
            for (int i = 0; i < 4; ++i) accum4(acc, r[i]);
            k += 4;
        }
        if (k + 1 < cnt) {                           // 2-wide tail
            int s0 = __ldg(my + 2 * k);
            int s1 = __ldg(my + 2 * (k + 1));
            uint2 r0 = hn[s0 * 32 + lane];
            uint2 r1 = hn[s1 * 32 + lane];
            accum4(acc, r0); accum4(acc, r1);
            k += 2;
        }
        if (k < cnt) {
            int s0 = __ldg(my + 2 * k);
            accum4(acc, hn[s0 * 32 + lane]);
        }
    }

    if (half == 1 && valid) sh_acc[pair][lane] = acc;
    __syncthreads();
    if (half == 1 || !valid) return;

    {   // combine partner's partial
        float4 p = sh_acc[pair][lane];
        acc.x += p.x; acc.y += p.y; acc.z += p.z; acc.w += p.w;
    }

    float inv_deg = 1.0f / fmaxf((float)(end - start), 1.0f);
    float4 c;
    c.x = acc.x * inv_deg; c.y = acc.y * inv_deg;
    c.z = acc.z * inv_deg; c.w = acc.w * inv_deg;

    // streaming reads: evict-first so hn16/csr stay L2-resident
    float4 bv = ldcs4(reinterpret_cast<const float4*>(b) + node * 32 + lane);

    // sum of squares over concat(b, c): 256 values, 8 per lane
    float ss = bv.x * bv.x + bv.y * bv.y + bv.z * bv.z + bv.w * bv.w
             +  c.x *  c.x +  c.y *  c.y +  c.z *  c.z +  c.w *  c.w;
    #pragma unroll
    for (int m = 16; m; m >>= 1)
        ss += __shfl_xor_sync(0xffffffffu, ss, m);

    float inv_l2 = 1.0f / fmaxf(sqrtf(ss), 1e-12f);
    float nrm    = __ldg(norm + node);

    // h_out = h + c * norm
    float4 hv = ldcs4(reinterpret_cast<const float4*>(h) + node * 32 + lane);
    float4 ho;
    ho.x = hv.x + c.x * nrm;
    ho.y = hv.y + c.y * nrm;
    ho.z = hv.z + c.z * nrm;
    ho.w = hv.w + c.w * nrm;
    stcs4(reinterpret_cast<float4*>(out) + node * 32 + lane, ho);

    // b_out = concat(b, c) / l2
    float* bout = out + (size_t)NN * DD;
    float4 b1; b1.x = bv.x * inv_l2; b1.y = bv.y * inv_l2;
               b1.z = bv.z * inv_l2; b1.w = bv.w * inv_l2;
    float4 b2; b2.x =  c.x * inv_l2; b2.y =  c.y * inv_l2;
               b2.z =  c.z * inv_l2; b2.w =  c.w * inv_l2;
    stcs4(reinterpret_cast<float4*>(bout) + node * 64 + lane,      b1);
    stcs4(reinterpret_cast<float4*>(bout) + node * 64 + 32 + lane, b2);
}

// ---------------------------------------------------------------------------
extern "C" void kernel_launch(void* const* d_in, const int* in_sizes, int n_in,
                              void* d_out, int out_size)
{
    const float* h    = (const float*)d_in[0];
    const float* b    = (const float*)d_in[1];
    const float* norm = (const float*)d_in[2];
    const int*   esrc = (const int*)  d_in[3];
    const int*   edst = (const int*)  d_in[4];
    float*       out  = (float*)d_out;
    int E = in_sizes[3];
    if (E > EE) E = EE;

    void* zero_ptr = nullptr;
    cudaGetSymbolAddress(&zero_ptr, g_zero);
    cudaMemsetAsync(zero_ptr, 0, (size_t)NN * 4 + SCAN_NB * 8);

    // fused prescale ∥ hist (8 edges/thread in hist)
    int preB  = (NN * (DD / 4) + 255) / 256;            // 12500
    int histB = (E + 2047) / 2048;
    fused_pre_hist_kernel<<<preB + histB, 256>>>(h, norm, edst, E, preB);

    // single-pass scan -> rowstart + cursor
    scan_onepass_kernel<<<SCAN_NB, SCAN_TPB>>>(E);

    // CSR fill (8 edges per thread, vectorized)
    int eb8 = (E / 8 + 255) / 256 + 1;
    fill_kernel<<<eb8, 256>>>(esrc, edst, E);

    // gather-mean + finalize: TWO warps per node
    long long threads = (long long)NN * 2 * 32;
    int blocks = (int)((threads + 255) / 256);
    gather_finalize_kernel<<<blocks, 256>>>(h, b, norm, out);
}

// round 13
// speedup vs baseline: 1.0859x; 1.0722x over previous
#include <cuda_runtime.h>
#include <cuda_fp16.h>

// ---------------------------------------------------------------------------
// ExpanderSimpleGraphSageLayer — CSR gather, fp16 staging
// R13: ticket-hist (fill has NO atomics), gather = R9 form + operand prefetch.
//
// Inputs (metadata order):
//   d_in[0] h        float32 [N, D]        N=100000, D=128
//   d_in[1] b        float32 [N, D]
//   d_in[2] norm     float32 [N, 1]
//   d_in[3] edge_src int32   [E]           E=1600000
//   d_in[4] edge_dst int32   [E]
// Output: h_out [N,D] followed by b_out [N,2D]  (float32, N*3D elements)
// ---------------------------------------------------------------------------

#define NN 100000
#define DD 128
#define EE 1600000

#define SCAN_TPB 256
#define SCAN_IPT 4
#define SCAN_PER_BLK (SCAN_TPB * SCAN_IPT)                 // 1024
#define SCAN_NB ((NN + SCAN_PER_BLK - 1) / SCAN_PER_BLK)   // 98  (< 148 SMs)

static __device__ __align__(16) __half g_hn16[NN * DD];  // fp16(h*norm), 25.6MB
static __device__ int    g_rowstart[NN + 1]; // CSR row offsets
static __device__ __align__(16) int g_ticket[EE];  // per-edge slot in dst group
static __device__ int    g_csr[EE];          // src ids grouped by dst

// zero-region: [count (NN int)] [scan state (SCAN_NB u64)] — one memset
static __device__ __align__(16) unsigned char g_zero[NN * 4 + SCAN_NB * 8];
#define G_COUNT ((int*)g_zero)
#define G_STATE ((unsigned long long*)(g_zero + NN * 4))
// state word: (status << 32) | value.  status: 0=empty, 1=aggregate, 2=inclusive

// ---- streaming load/store helpers -----------------------------------------
__device__ __forceinline__ float4 ldcs4(const float4* p) {
    float4 v;
    asm volatile("ld.global.cs.v4.f32 {%0,%1,%2,%3}, [%4];"
                 : "=f"(v.x), "=f"(v.y), "=f"(v.z), "=f"(v.w) : "l"(p));
    return v;
}
__device__ __forceinline__ void stcs4(float4* p, float4 v) {
    asm volatile("st.global.cs.v4.f32 [%0], {%1,%2,%3,%4};"
                 :: "l"(p), "f"(v.x), "f"(v.y), "f"(v.z), "f"(v.w) : "memory");
}

// accumulate 4 halves (one uint2) into float4
__device__ __forceinline__ void accum4(float4& a, uint2 r) {
    float2 f0 = __half22float2(*reinterpret_cast<__half2*>(&r.x));
    float2 f1 = __half22float2(*reinterpret_cast<__half2*>(&r.y));
    a.x += f0.x; a.y += f0.y; a.z += f1.x; a.w += f1.y;
}

// ---- phase 1: fused  prescale (blocks [0,preB))  ∥  ticket-hist (rest) ----
__global__ void __launch_bounds__(256)
fused_pre_hist_kernel(const float* __restrict__ h, const float* __restrict__ norm,
                      const int* __restrict__ dst, int E, int preB)
{
    if ((int)blockIdx.x < preB) {
        int idx = blockIdx.x * 256 + threadIdx.x;          // one float4
        if (idx >= NN * (DD / 4)) return;
        int row = idx >> 5;                                // 32 float4 per row
        float4 v = ldcs4(reinterpret_cast<const float4*>(h) + idx);
        float  s = __ldg(norm + row);
        __half2 lo = __floats2half2_rn(v.x * s, v.y * s);
        __half2 hi = __floats2half2_rn(v.z * s, v.w * s);
        uint2 u;
        u.x = *reinterpret_cast<unsigned*>(&lo);
        u.y = *reinterpret_cast<unsigned*>(&hi);
        reinterpret_cast<uint2*>(g_hn16)[idx] = u;
    } else {
        int base = ((blockIdx.x - preB) * 256 + threadIdx.x) * 8;
        if (base + 8 <= E) {
            const int4* d4 = reinterpret_cast<const int4*>(dst + base);
            int4 da = __ldg(d4), db = __ldg(d4 + 1);
            int4 ta, tb;
            ta.x = atomicAdd(&G_COUNT[da.x], 1);
            ta.y = atomicAdd(&G_COUNT[da.y], 1);
            ta.z = atomicAdd(&G_COUNT[da.z], 1);
            ta.w = atomicAdd(&G_COUNT[da.w], 1);
            tb.x = atomicAdd(&G_COUNT[db.x], 1);
            tb.y = atomicAdd(&G_COUNT[db.y], 1);
            tb.z = atomicAdd(&G_COUNT[db.z], 1);
            tb.w = atomicAdd(&G_COUNT[db.w], 1);
            int4* t4 = reinterpret_cast<int4*>(g_ticket + base);
            t4[0] = ta; t4[1] = tb;
        } else {
            for (int e = base; e < E; ++e)
                g_ticket[e] = atomicAdd(&G_COUNT[__ldg(dst + e)], 1);
        }
    }
}

// ---- phase 2: single-pass exclusive scan (decoupled lookback) --------------
__global__ void __launch_bounds__(SCAN_TPB)
scan_onepass_kernel(int E)
{
    int blk  = blockIdx.x;
    int lane = threadIdx.x & 31, wid = threadIdx.x >> 5;
    int base = blk * SCAN_PER_BLK + threadIdx.x * SCAN_IPT;

    int c[SCAN_IPT];
    if (base + SCAN_IPT <= NN) {
        int4 cv = *reinterpret_cast<const int4*>(G_COUNT + base);
        c[0] = cv.x; c[1] = cv.y; c[2] = cv.z; c[3] = cv.w;
    } else {
        #pragma unroll
        for (int i = 0; i < SCAN_IPT; ++i) {
            int idx = base + i;
            c[i] = (idx < NN) ? G_COUNT[idx] : 0;
        }
    }
    int t0 = c[0];
    int t1 = t0 + c[1];
    int t2 = t1 + c[2];
    int t3 = t2 + c[3];
    int tot = t3;

    // warp inclusive scan of per-thread totals
    int x = tot;
    #pragma unroll
    for (int d = 1; d < 32; d <<= 1) {
        int y = __shfl_up_sync(0xffffffffu, x, d);
        if (lane >= d) x += y;
    }
    int warp_excl = x - tot;

    __shared__ int wsum[SCAN_TPB / 32];
    __shared__ int woff[SCAN_TPB / 32];
    __shared__ int sh_btotal;
    __shared__ unsigned sh_excl;
    if (lane == 31) wsum[wid] = x;
    __syncthreads();
    if (threadIdx.x == 0) {
        int r = 0;
        #pragma unroll
        for (int j = 0; j < SCAN_TPB / 32; ++j) { woff[j] = r; r += wsum[j]; }
        sh_btotal = r;
        sh_excl = 0;
    }
    __syncthreads();
    int btotal = sh_btotal;

    if (blk == 0) {
        if (threadIdx.x == 0) {
            __threadfence();
            *(volatile unsigned long long*)&G_STATE[0] =
                (2ull << 32) | (unsigned)btotal;
        }
    } else if (wid == 0) {
        if (lane == 0) {
            __threadfence();
            *(volatile unsigned long long*)&G_STATE[blk] =
                (1ull << 32) | (unsigned)btotal;
        }
        unsigned running = 0;
        int idx = blk - 1;
        for (;;) {
            int j = idx - lane;
            bool valid = j >= 0;
            unsigned long long st;
            for (;;) {
                st = valid ? *(volatile const unsigned long long*)&G_STATE[j]
                           : (2ull << 32);
                if (!__any_sync(0xffffffffu, (unsigned)(st >> 32) == 0u)) break;
            }
            unsigned stat = (unsigned)(st >> 32);
            unsigned val  = (unsigned)st;
            unsigned mask2 = __ballot_sync(0xffffffffu, stat == 2u);
            if (mask2) {
                int firstIncl = __ffs(mask2) - 1;   // closest inclusive
                unsigned contrib = (lane <= firstIncl) ? val : 0u;
                #pragma unroll
                for (int m = 16; m; m >>= 1)
                    contrib += __shfl_xor_sync(0xffffffffu, contrib, m);
                running += contrib;
                break;
            } else {
                unsigned contrib = val;
                #pragma unroll
                for (int m = 16; m; m >>= 1)
                    contrib += __shfl_xor_sync(0xffffffffu, contrib, m);
                running += contrib;
                idx -= 32;
            }
        }
        if (lane == 0) {
            sh_excl = running;
            __threadfence();
            *(volatile unsigned long long*)&G_STATE[blk] =
                (2ull << 32) | (unsigned)(running + btotal);
        }
    }
    __syncthreads();
    unsigned excl = sh_excl;

    int off = (int)excl + woff[wid] + warp_excl;
    int ex[SCAN_IPT] = { off, off + t0, off + t1, off + t2 };
    #pragma unroll
    for (int i = 0; i < SCAN_IPT; ++i) {
        int idx = base + i;
        if (idx < NN) g_rowstart[idx] = ex[i];
    }
    if (blk == 0 && threadIdx.x == 0) g_rowstart[NN] = E;
}

// ---- phase 3: fill CSR — NO atomics (rowstart[d] + precomputed ticket) -----
__global__ void __launch_bounds__(256)
fill_kernel(const int* __restrict__ src, const int* __restrict__ dst, int E)
{
    int base = (blockIdx.x * blockDim.x + threadIdx.x) * 8;
    if (base + 8 <= E) {
        const int4* s4 = reinterpret_cast<const int4*>(src + base);
        const int4* d4 = reinterpret_cast<const int4*>(dst + base);
        const int4* t4 = reinterpret_cast<const int4*>(g_ticket + base);
        int4 sa = __ldg(s4), sb = __ldg(s4 + 1);
        int4 da = __ldg(d4), db = __ldg(d4 + 1);
        int4 ta = t4[0],     tb = t4[1];
        int s[8] = { sa.x, sa.y, sa.z, sa.w, sb.x, sb.y, sb.z, sb.w };
        int d[8] = { da.x, da.y, da.z, da.w, db.x, db.y, db.z, db.w };
        int t[8] = { ta.x, ta.y, ta.z, ta.w, tb.x, tb.y, tb.z, tb.w };
        int r[8];
        #pragma unroll
        for (int i = 0; i < 8; ++i) r[i] = __ldg(g_rowstart + d[i]);
        #pragma unroll
        for (int i = 0; i < 8; ++i) g_csr[r[i] + t[i]] = s[i];
    } else {
        for (int e = base; e < E; ++e) {
            int d = __ldg(dst + e);
            g_csr[__ldg(g_rowstart + d) + g_ticket[e]] = __ldg(src + e);
        }
    }
}

// ---- phase 4: fused gather-mean + finalize (one warp per node, R9 form) ----
__global__ void __launch_bounds__(256)
gather_finalize_kernel(const float* __restrict__ h, const float* __restrict__ b,
                       const float* __restrict__ norm, float* __restrict__ out)
{
    int node = (blockIdx.x * blockDim.x + threadIdx.x) >> 5;
    int lane = threadIdx.x & 31;
    if (node >= NN) return;

    // prefetch streaming operands: DRAM latency overlaps the gather loop
    float4 bv  = ldcs4(reinterpret_cast<const float4*>(b) + node * 32 + lane);
    float4 hv  = ldcs4(reinterpret_cast<const float4*>(h) + node * 32 + lane);
    float  nrm = __ldg(norm + node);

    int start = __ldg(g_rowstart + node);
    int end   = __ldg(g_rowstart + node + 1);

    const uint2* hn = reinterpret_cast<const uint2*>(g_hn16);   // 32 uint2/row
    float4 acc = make_float4(0.f, 0.f, 0.f, 0.f);

    int e = start;
    for (; e + 7 < end; e += 8) {                   // 8 rows in flight
        int s[8];
        #pragma unroll
        for (int i = 0; i < 8; ++i) s[i] = __ldg(g_csr + e + i);
        uint2 r[8];
        #pragma unroll
        for (int i = 0; i < 8; ++i) r[i] = hn[s[i] * 32 + lane];
        #pragma unroll
        for (int i = 0; i < 8; ++i) accum4(acc, r[i]);
    }
    if (e + 3 < end) {                              // 4-wide tail
        int s[4];
        #pragma unroll
        for (int i = 0; i < 4; ++i) s[i] = __ldg(g_csr + e + i);
        uint2 r[4];
        #pragma unroll
        for (int i = 0; i < 4; ++i) r[i] = hn[s[i] * 32 + lane];
        #pragma unroll
        for (int i = 0; i < 4; ++i) accum4(acc, r[i]);
        e += 4;
    }
    if (e + 1 < end) {                              // 2-wide tail
        int s0 = __ldg(g_csr + e);
        int s1 = __ldg(g_csr + e + 1);
        uint2 r0 = hn[s0 * 32 + lane];
        uint2 r1 = hn[s1 * 32 + lane];
        accum4(acc, r0); accum4(acc, r1);
        e += 2;
    }
    if (e < end) {
        int s0 = __ldg(g_csr + e);
        accum4(acc, hn[s0 * 32 + lane]);
    }

    float inv_deg = 1.0f / fmaxf((float)(end - start), 1.0f);
    float4 c;
    c.x = acc.x * inv_deg; c.y = acc.y * inv_deg;
    c.z = acc.z * inv_deg; c.w = acc.w * inv_deg;

    // sum of squares over concat(b, c): 256 values, 8 per lane
    float ss = bv.x * bv.x + bv.y * bv.y + bv.z * bv.z + bv.w * bv.w
             +  c.x *  c.x +  c.y *  c.y +  c.z *  c.z +  c.w *  c.w;
    #pragma unroll
    for (int m = 16; m; m >>= 1)
        ss += __shfl_xor_sync(0xffffffffu, ss, m);

    float inv_l2 = 1.0f / fmaxf(sqrtf(ss), 1e-12f);

    // h_out = h + c * norm
    float4 ho;
    ho.x = hv.x + c.x * nrm;
    ho.y = hv.y + c.y * nrm;
    ho.z = hv.z + c.z * nrm;
    ho.w = hv.w + c.w * nrm;
    stcs4(reinterpret_cast<float4*>(out) + node * 32 + lane, ho);

    // b_out = concat(b, c) / l2
    float* bout = out + (size_t)NN * DD;
    float4 b1; b1.x = bv.x * inv_l2; b1.y = bv.y * inv_l2;
               b1.z = bv.z * inv_l2; b1.w = bv.w * inv_l2;
    float4 b2; b2.x =  c.x * inv_l2; b2.y =  c.y * inv_l2;
               b2.z =  c.z * inv_l2; b2.w =  c.w * inv_l2;
    stcs4(reinterpret_cast<float4*>(bout) + node * 64 + lane,      b1);
    stcs4(reinterpret_cast<float4*>(bout) + node * 64 + 32 + lane, b2);
}

// ---------------------------------------------------------------------------
extern "C" void kernel_launch(void* const* d_in, const int* in_sizes, int n_in,
                              void* d_out, int out_size)
{
    const float* h    = (const float*)d_in[0];
    const float* b    = (const float*)d_in[1];
    const float* norm = (const float*)d_in[2];
    const int*   esrc = (const int*)  d_in[3];
    const int*   edst = (const int*)  d_in[4];
    float*       out  = (float*)d_out;
    int E = in_sizes[3];
    if (E > EE) E = EE;

    void* zero_ptr = nullptr;
    cudaGetSymbolAddress(&zero_ptr, g_zero);
    cudaMemsetAsync(zero_ptr, 0, (size_t)NN * 4 + SCAN_NB * 8);

    // fused prescale ∥ ticket-hist (8 edges/thread)
    int preB  = (NN * (DD / 4) + 255) / 256;            // 12500
    int histB = (E + 2047) / 2048;
    fused_pre_hist_kernel<<<preB + histB, 256>>>(h, norm, edst, E, preB);

    // single-pass scan -> rowstart
    scan_onepass_kernel<<<SCAN_NB, SCAN_TPB>>>(E);

    // CSR fill (no atomics: rowstart + ticket)
    int eb8 = (E / 8 + 255) / 256 + 1;
    fill_kernel<<<eb8, 256>>>(esrc, edst, E);

    // fused gather-mean + finalize: one warp per node
    long long threads = (long long)NN * 32;
    int blocks = (int)((threads + 255) / 256);
    gather_finalize_kernel<<<blocks, 256>>>(h, b, norm, out);
}

// round 14
// speedup vs baseline: 1.1434x; 1.0530x over previous
#include <cuda_runtime.h>
#include <cuda_fp16.h>

// ---------------------------------------------------------------------------
// ExpanderSimpleGraphSageLayer — CSR gather, fp16 staging
// R14: best-of assembly — R9 gather (LTS-capped, loads after loop) +
//      R13 ticket-hist / atomic-free fill + single-pass lookback scan.
//
// Inputs (metadata order):
//   d_in[0] h        float32 [N, D]        N=100000, D=128
//   d_in[1] b        float32 [N, D]
//   d_in[2] norm     float32 [N, 1]
//   d_in[3] edge_src int32   [E]           E=1600000
//   d_in[4] edge_dst int32   [E]
// Output: h_out [N,D] followed by b_out [N,2D]  (float32, N*3D elements)
// ---------------------------------------------------------------------------

#define NN 100000
#define DD 128
#define EE 1600000

#define SCAN_TPB 256
#define SCAN_IPT 4
#define SCAN_PER_BLK (SCAN_TPB * SCAN_IPT)                 // 1024
#define SCAN_NB ((NN + SCAN_PER_BLK - 1) / SCAN_PER_BLK)   // 98  (< 148 SMs)

static __device__ __align__(16) __half g_hn16[NN * DD];  // fp16(h*norm), 25.6MB
static __device__ int    g_rowstart[NN + 1]; // CSR row offsets
static __device__ __align__(16) int g_ticket[EE];  // per-edge slot in dst group
static __device__ int    g_csr[EE];          // src ids grouped by dst

// zero-region: [count (NN int)] [scan state (SCAN_NB u64)] — one memset
static __device__ __align__(16) unsigned char g_zero[NN * 4 + SCAN_NB * 8];
#define G_COUNT ((int*)g_zero)
#define G_STATE ((unsigned long long*)(g_zero + NN * 4))
// state word: (status << 32) | value.  status: 0=empty, 1=aggregate, 2=inclusive

// ---- streaming load/store helpers -----------------------------------------
__device__ __forceinline__ float4 ldcs4(const float4* p) {
    float4 v;
    asm volatile("ld.global.cs.v4.f32 {%0,%1,%2,%3}, [%4];"
                 : "=f"(v.x), "=f"(v.y), "=f"(v.z), "=f"(v.w) : "l"(p));
    return v;
}
__device__ __forceinline__ void stcs4(float4* p, float4 v) {
    asm volatile("st.global.cs.v4.f32 [%0], {%1,%2,%3,%4};"
                 :: "l"(p), "f"(v.x), "f"(v.y), "f"(v.z), "f"(v.w) : "memory");
}

// accumulate 4 halves (one uint2) into float4
__device__ __forceinline__ void accum4(float4& a, uint2 r) {
    float2 f0 = __half22float2(*reinterpret_cast<__half2*>(&r.x));
    float2 f1 = __half22float2(*reinterpret_cast<__half2*>(&r.y));
    a.x += f0.x; a.y += f0.y; a.z += f1.x; a.w += f1.y;
}

// ---- phase 1: fused  prescale (blocks [0,preB))  ∥  ticket-hist (rest) ----
__global__ void __launch_bounds__(256)
fused_pre_hist_kernel(const float* __restrict__ h, const float* __restrict__ norm,
                      const int* __restrict__ dst, int E, int preB)
{
    if ((int)blockIdx.x < preB) {
        int idx = blockIdx.x * 256 + threadIdx.x;          // one float4
        if (idx >= NN * (DD / 4)) return;
        int row = idx >> 5;                                // 32 float4 per row
        float4 v = ldcs4(reinterpret_cast<const float4*>(h) + idx);
        float  s = __ldg(norm + row);
        __half2 lo = __floats2half2_rn(v.x * s, v.y * s);
        __half2 hi = __floats2half2_rn(v.z * s, v.w * s);
        uint2 u;
        u.x = *reinterpret_cast<unsigned*>(&lo);
        u.y = *reinterpret_cast<unsigned*>(&hi);
        reinterpret_cast<uint2*>(g_hn16)[idx] = u;
    } else {
        int base = ((blockIdx.x - preB) * 256 + threadIdx.x) * 8;
        if (base + 8 <= E) {
            const int4* d4 = reinterpret_cast<const int4*>(dst + base);
            int4 da = __ldg(d4), db = __ldg(d4 + 1);
            int4 ta, tb;
            ta.x = atomicAdd(&G_COUNT[da.x], 1);
            ta.y = atomicAdd(&G_COUNT[da.y], 1);
            ta.z = atomicAdd(&G_COUNT[da.z], 1);
            ta.w = atomicAdd(&G_COUNT[da.w], 1);
            tb.x = atomicAdd(&G_COUNT[db.x], 1);
            tb.y = atomicAdd(&G_COUNT[db.y], 1);
            tb.z = atomicAdd(&G_COUNT[db.z], 1);
            tb.w = atomicAdd(&G_COUNT[db.w], 1);
            int4* t4 = reinterpret_cast<int4*>(g_ticket + base);
            t4[0] = ta; t4[1] = tb;
        } else {
            for (int e = base; e < E; ++e)
                g_ticket[e] = atomicAdd(&G_COUNT[__ldg(dst + e)], 1);
        }
    }
}

// ---- phase 2: single-pass exclusive scan (decoupled lookback) --------------
__global__ void __launch_bounds__(SCAN_TPB)
scan_onepass_kernel(int E)
{
    int blk  = blockIdx.x;
    int lane = threadIdx.x & 31, wid = threadIdx.x >> 5;
    int base = blk * SCAN_PER_BLK + threadIdx.x * SCAN_IPT;

    int c[SCAN_IPT];
    if (base + SCAN_IPT <= NN) {
        int4 cv = *reinterpret_cast<const int4*>(G_COUNT + base);
        c[0] = cv.x; c[1] = cv.y; c[2] = cv.z; c[3] = cv.w;
    } else {
        #pragma unroll
        for (int i = 0; i < SCAN_IPT; ++i) {
            int idx = base + i;
            c[i] = (idx < NN) ? G_COUNT[idx] : 0;
        }
    }
    int t0 = c[0];
    int t1 = t0 + c[1];
    int t2 = t1 + c[2];
    int t3 = t2 + c[3];
    int tot = t3;

    // warp inclusive scan of per-thread totals
    int x = tot;
    #pragma unroll
    for (int d = 1; d < 32; d <<= 1) {
        int y = __shfl_up_sync(0xffffffffu, x, d);
        if (lane >= d) x += y;
    }
    int warp_excl = x - tot;

    __shared__ int wsum[SCAN_TPB / 32];
    __shared__ int woff[SCAN_TPB / 32];
    __shared__ int sh_btotal;
    __shared__ unsigned sh_excl;
    if (lane == 31) wsum[wid] = x;
    __syncthreads();
    if (threadIdx.x == 0) {
        int r = 0;
        #pragma unroll
        for (int j = 0; j < SCAN_TPB / 32; ++j) { woff[j] = r; r += wsum[j]; }
        sh_btotal = r;
        sh_excl = 0;
    }
    __syncthreads();
    int btotal = sh_btotal;

    if (blk == 0) {
        if (threadIdx.x == 0) {
            __threadfence();
            *(volatile unsigned long long*)&G_STATE[0] =
                (2ull << 32) | (unsigned)btotal;
        }
    } else if (wid == 0) {
        if (lane == 0) {
            __threadfence();
            *(volatile unsigned long long*)&G_STATE[blk] =
                (1ull << 32) | (unsigned)btotal;
        }
        unsigned running = 0;
        int idx = blk - 1;
        for (;;) {
            int j = idx - lane;
            bool valid = j >= 0;
            unsigned long long st;
            for (;;) {
                st = valid ? *(volatile const unsigned long long*)&G_STATE[j]
                           : (2ull << 32);
                if (!__any_sync(0xffffffffu, (unsigned)(st >> 32) == 0u)) break;
            }
            unsigned stat = (unsigned)(st >> 32);
            unsigned val  = (unsigned)st;
            unsigned mask2 = __ballot_sync(0xffffffffu, stat == 2u);
            if (mask2) {
                int firstIncl = __ffs(mask2) - 1;   // closest inclusive
                unsigned contrib = (lane <= firstIncl) ? val : 0u;
                #pragma unroll
                for (int m = 16; m; m >>= 1)
                    contrib += __shfl_xor_sync(0xffffffffu, contrib, m);
                running += contrib;
                break;
            } else {
                unsigned contrib = val;
                #pragma unroll
                for (int m = 16; m; m >>= 1)
                    contrib += __shfl_xor_sync(0xffffffffu, contrib, m);
                running += contrib;
                idx -= 32;
            }
        }
        if (lane == 0) {
            sh_excl = running;
            __threadfence();
            *(volatile unsigned long long*)&G_STATE[blk] =
                (2ull << 32) | (unsigned)(running + btotal);
        }
    }
    __syncthreads();
    unsigned excl = sh_excl;

    int off = (int)excl + woff[wid] + warp_excl;
    int ex[SCAN_IPT] = { off, off + t0, off + t1, off + t2 };
    #pragma unroll
    for (int i = 0; i < SCAN_IPT; ++i) {
        int idx = base + i;
        if (idx < NN) g_rowstart[idx] = ex[i];
    }
    if (blk == 0 && threadIdx.x == 0) g_rowstart[NN] = E;
}

// ---- phase 3: fill CSR — NO atomics (rowstart[d] + precomputed ticket) -----
__global__ void __launch_bounds__(256)
fill_kernel(const int* __restrict__ src, const int* __restrict__ dst, int E)
{
    int base = (blockIdx.x * blockDim.x + threadIdx.x) * 8;
    if (base + 8 <= E) {
        const int4* s4 = reinterpret_cast<const int4*>(src + base);
        const int4* d4 = reinterpret_cast<const int4*>(dst + base);
        const int4* t4 = reinterpret_cast<const int4*>(g_ticket + base);
        int4 sa = __ldg(s4), sb = __ldg(s4 + 1);
        int4 da = __ldg(d4), db = __ldg(d4 + 1);
        int4 ta = t4[0],     tb = t4[1];
        int s[8] = { sa.x, sa.y, sa.z, sa.w, sb.x, sb.y, sb.z, sb.w };
        int d[8] = { da.x, da.y, da.z, da.w, db.x, db.y, db.z, db.w };
        int t[8] = { ta.x, ta.y, ta.z, ta.w, tb.x, tb.y, tb.z, tb.w };
        int r[8];
        #pragma unroll
        for (int i = 0; i < 8; ++i) r[i] = __ldg(g_rowstart + d[i]);
        #pragma unroll
        for (int i = 0; i < 8; ++i) g_csr[r[i] + t[i]] = s[i];
    } else {
        for (int e = base; e < E; ++e) {
            int d = __ldg(dst + e);
            g_csr[__ldg(g_rowstart + d) + g_ticket[e]] = __ldg(src + e);
        }
    }
}

// ---- phase 4: fused gather-mean + finalize (one warp per node, R9 form) ----
__global__ void __launch_bounds__(256)
gather_finalize_kernel(const float* __restrict__ h, const float* __restrict__ b,
                       const float* __restrict__ norm, float* __restrict__ out)
{
    int node = (blockIdx.x * blockDim.x + threadIdx.x) >> 5;
    int lane = threadIdx.x & 31;
    if (node >= NN) return;

    int start = __ldg(g_rowstart + node);
    int end   = __ldg(g_rowstart + node + 1);

    const uint2* hn = reinterpret_cast<const uint2*>(g_hn16);   // 32 uint2/row
    float4 acc = make_float4(0.f, 0.f, 0.f, 0.f);

    int e = start;
    for (; e + 7 < end; e += 8) {                   // 8 rows in flight
        int s[8];
        #pragma unroll
        for (int i = 0; i < 8; ++i) s[i] = __ldg(g_csr + e + i);
        uint2 r[8];
        #pragma unroll
        for (int i = 0; i < 8; ++i) r[i] = hn[s[i] * 32 + lane];
        #pragma unroll
        for (int i = 0; i < 8; ++i) accum4(acc, r[i]);
    }
    if (e + 3 < end) {                              // 4-wide tail
        int s[4];
        #pragma unroll
        for (int i = 0; i < 4; ++i) s[i] = __ldg(g_csr + e + i);
        uint2 r[4];
        #pragma unroll
        for (int i = 0; i < 4; ++i) r[i] = hn[s[i] * 32 + lane];
        #pragma unroll
        for (int i = 0; i < 4; ++i) accum4(acc, r[i]);
        e += 4;
    }
    if (e + 1 < end) {                              // 2-wide tail
        int s0 = __ldg(g_csr + e);
        int s1 = __ldg(g_csr + e + 1);
        uint2 r0 = hn[s0 * 32 + lane];
        uint2 r1 = hn[s1 * 32 + lane];
        accum4(acc, r0); accum4(acc, r1);
        e += 2;
    }
    if (e < end) {
        int s0 = __ldg(g_csr + e);
        accum4(acc, hn[s0 * 32 + lane]);
    }

    float inv_deg = 1.0f / fmaxf((float)(end - start), 1.0f);
    float4 c;
    c.x = acc.x * inv_deg; c.y = acc.y * inv_deg;
    c.z = acc.z * inv_deg; c.w = acc.w * inv_deg;

    // streaming reads: evict-first so hn16/csr stay L2-resident
    float4 bv = ldcs4(reinterpret_cast<const float4*>(b) + node * 32 + lane);

    // sum of squares over concat(b, c): 256 values, 8 per lane
    float ss = bv.x * bv.x + bv.y * bv.y + bv.z * bv.z + bv.w * bv.w
             +  c.x *  c.x +  c.y *  c.y +  c.z *  c.z +  c.w *  c.w;
    #pragma unroll
    for (int m = 16; m; m >>= 1)
        ss += __shfl_xor_sync(0xffffffffu, ss, m);

    float inv_l2 = 1.0f / fmaxf(sqrtf(ss), 1e-12f);
    float nrm    = __ldg(norm + node);

    // h_out = h + c * norm
    float4 hv = ldcs4(reinterpret_cast<const float4*>(h) + node * 32 + lane);
    float4 ho;
    ho.x = hv.x + c.x * nrm;
    ho.y = hv.y + c.y * nrm;
    ho.z = hv.z + c.z * nrm;
    ho.w = hv.w + c.w * nrm;
    stcs4(reinterpret_cast<float4*>(out) + node * 32 + lane, ho);

    // b_out = concat(b, c) / l2
    float* bout = out + (size_t)NN * DD;
    float4 b1; b1.x = bv.x * inv_l2; b1.y = bv.y * inv_l2;
               b1.z = bv.z * inv_l2; b1.w = bv.w * inv_l2;
    float4 b2; b2.x =  c.x * inv_l2; b2.y =  c.y * inv_l2;
               b2.z =  c.z * inv_l2; b2.w =  c.w * inv_l2;
    stcs4(reinterpret_cast<float4*>(bout) + node * 64 + lane,      b1);
    stcs4(reinterpret_cast<float4*>(bout) + node * 64 + 32 + lane, b2);
}

// ---------------------------------------------------------------------------
extern "C" void kernel_launch(void* const* d_in, const int* in_sizes, int n_in,
                              void* d_out, int out_size)
{
    const float* h    = (const float*)d_in[0];
    const float* b    = (const float*)d_in[1];
    const float* norm = (const float*)d_in[2];
    const int*   esrc = (const int*)  d_in[3];
    const int*   edst = (const int*)  d_in[4];
    float*       out  = (float*)d_out;
    int E = in_sizes[3];
    if (E > EE) E = EE;

    void* zero_ptr = nullptr;
    cudaGetSymbolAddress(&zero_ptr, g_zero);
    cudaMemsetAsync(zero_ptr, 0, (size_t)NN * 4 + SCAN_NB * 8);

    // fused prescale ∥ ticket-hist (8 edges/thread)
    int preB  = (NN * (DD / 4) + 255) / 256;            // 12500
    int histB = (E + 2047) / 2048;
    fused_pre_hist_kernel<<<preB + histB, 256>>>(h, norm, edst, E, preB);

    // single-pass scan -> rowstart
    scan_onepass_kernel<<<SCAN_NB, SCAN_TPB>>>(E);

    // CSR fill (no atomics: rowstart + ticket)
    int eb8 = (E / 8 + 255) / 256 + 1;
    fill_kernel<<<eb8, 256>>>(esrc, edst, E);

    // fused gather-mean + finalize: one warp per node
    long long threads = (long long)NN * 32;
    int blocks = (int)((threads + 255) / 256);
    gather_finalize_kernel<<<blocks, 256>>>(h, b, norm, out);
}